// round 1
// baseline (speedup 1.0000x reference)
#include <cuda_runtime.h>
#include <cstdint>

// Problem constants
#define BATCH 4
#define CIN   256
#define HDIM  64
#define WDIM  64
#define HW    4096          // 64*64
#define OUTC  256
#define KKPOS 9             // 3x3
#define CKDIM 2304          // CIN * 9
#define NOFF  27            // 3*K*K offset-conv output channels

// ---------------------------------------------------------------------------
// Scratch (static __device__ arrays: allocation inside kernel_launch is banned)
// ---------------------------------------------------------------------------
// Per-(b, kpos, hw) bilinear sampling record: 4 clamped flat indices into the
// 64x64 plane + 4 bilinear weights (mask folded in, zeroed when out of range).
__device__ int4   g_rec_idx[BATCH * KKPOS * HW];     // 2.36 MB
__device__ float4 g_rec_w  [BATCH * KKPOS * HW];     // 2.36 MB
// Materialized deformable im2col matrix, K-major rows: val[b][hw][ck]
__device__ float  g_val[(size_t)BATCH * HW * CKDIM]; // 151 MB

// ---------------------------------------------------------------------------
// Kernel 1: offset conv (27ch 3x3 over C=256) + sampling-record build
// One thread per (b, h, w). 27 accumulators amortize x loads across channels.
// ---------------------------------------------------------------------------
__global__ __launch_bounds__(128)
void offset_kernel(const float* __restrict__ x,
                   const float* __restrict__ w_off,
                   const float* __restrict__ b_off)
{
    __shared__ float s_w[NOFF * 16 * KKPOS];   // 27*16*9 floats = 15.2 KB chunk

    const int gid = blockIdx.x * blockDim.x + threadIdx.x;   // 0..16383
    const int b  = gid >> 12;
    const int hw = gid & 4095;
    const int y  = hw >> 6;
    const int xw = hw & 63;

    float acc[NOFF];
#pragma unroll
    for (int i = 0; i < NOFF; i++) acc[i] = 0.f;

    const float* xb = x + (size_t)b * CIN * HW;

    for (int c0 = 0; c0 < CIN; c0 += 16) {
        __syncthreads();
        // stage w_off[:, c0:c0+16, :] into smem, layout [oc][cc][j]
        for (int i = threadIdx.x; i < NOFF * 16 * KKPOS; i += blockDim.x) {
            int oc  = i / (16 * KKPOS);
            int rem = i - oc * (16 * KKPOS);          // cc*9 + j
            s_w[i] = w_off[oc * (CIN * KKPOS) + c0 * KKPOS + rem];
        }
        __syncthreads();

        for (int cc = 0; cc < 16; cc++) {
            const float* xp = xb + (size_t)(c0 + cc) * HW;
            float v[9];
#pragma unroll
            for (int j = 0; j < 9; j++) {
                int dy = j / 3 - 1, dx = j % 3 - 1;
                int yy = y + dy, xx = xw + dx;
                v[j] = (yy >= 0 && yy < HDIM && xx >= 0 && xx < WDIM)
                         ? xp[yy * WDIM + xx] : 0.f;
            }
            const float* sw = &s_w[cc * KKPOS];
#pragma unroll
            for (int oc = 0; oc < NOFF; oc++) {
                float s = 0.f;
#pragma unroll
                for (int j = 0; j < 9; j++)
                    s += sw[oc * (16 * KKPOS) + j] * v[j];
                acc[oc] += s;
            }
        }
    }

    // Build sampling records.
    // dy = om[2k], dx = om[2k+1], mask = sigmoid(om[18+k])
#pragma unroll
    for (int kp = 0; kp < KKPOS; kp++) {
        float dy = acc[2 * kp]     + b_off[2 * kp];
        float dx = acc[2 * kp + 1] + b_off[2 * kp + 1];
        float mm = acc[18 + kp]    + b_off[18 + kp];
        float mask = 1.f / (1.f + __expf(-mm));

        float py = (float)(y  - 1 + kp / 3) + dy;
        float px = (float)(xw - 1 + kp % 3) + dx;
        float y0f = floorf(py), x0f = floorf(px);
        float ly = py - y0f,   lx = px - x0f;
        int y0 = (int)y0f, x0 = (int)x0f;

        int4 idx; float4 wv;
        {
            int yy = y0, xx = x0;
            bool ok = (yy >= 0 && yy < HDIM && xx >= 0 && xx < WDIM);
            int yc = min(max(yy, 0), HDIM - 1), xc = min(max(xx, 0), WDIM - 1);
            idx.x = yc * WDIM + xc;
            wv.x = ok ? (1.f - ly) * (1.f - lx) * mask : 0.f;
        }
        {
            int yy = y0, xx = x0 + 1;
            bool ok = (yy >= 0 && yy < HDIM && xx >= 0 && xx < WDIM);
            int yc = min(max(yy, 0), HDIM - 1), xc = min(max(xx, 0), WDIM - 1);
            idx.y = yc * WDIM + xc;
            wv.y = ok ? (1.f - ly) * lx * mask : 0.f;
        }
        {
            int yy = y0 + 1, xx = x0;
            bool ok = (yy >= 0 && yy < HDIM && xx >= 0 && xx < WDIM);
            int yc = min(max(yy, 0), HDIM - 1), xc = min(max(xx, 0), WDIM - 1);
            idx.z = yc * WDIM + xc;
            wv.z = ok ? ly * (1.f - lx) * mask : 0.f;
        }
        {
            int yy = y0 + 1, xx = x0 + 1;
            bool ok = (yy >= 0 && yy < HDIM && xx >= 0 && xx < WDIM);
            int yc = min(max(yy, 0), HDIM - 1), xc = min(max(xx, 0), WDIM - 1);
            idx.w = yc * WDIM + xc;
            wv.w = ok ? ly * lx * mask : 0.f;
        }

        int r = ((b * KKPOS + kp) << 12) + hw;
        g_rec_idx[r] = idx;
        g_rec_w[r]   = wv;
    }
}

// ---------------------------------------------------------------------------
// Kernel 2: bilinear gather -> g_val[b][hw][ck]  (K-major rows)
// Gather phase reads with lanes along hw (near-coalesced: sample position
// ~ hw + small offset); SMEM transpose makes the K-major write coalesced.
// ---------------------------------------------------------------------------
__global__ __launch_bounds__(256)
void gather_kernel(const float* __restrict__ x)
{
    __shared__ float s[32][33];

    const int b   = blockIdx.z;
    const int n0  = blockIdx.y * 32;     // hw tile
    const int ck0 = blockIdx.x * 32;     // ck tile
    const float* xb = x + (size_t)b * CIN * HW;

    for (int i = threadIdx.x; i < 1024; i += 256) {
        int ckl = i >> 5;                 // fixed per warp
        int nl  = i & 31;                 // lane-varying -> coalesced
        int ck  = ck0 + ckl;
        int c   = ck / KKPOS;
        int kp  = ck - c * KKPOS;
        int n   = n0 + nl;
        int r   = ((b * KKPOS + kp) << 12) + n;
        int4   id = g_rec_idx[r];
        float4 wv = g_rec_w[r];
        const float* xp = xb + (size_t)c * HW;
        s[ckl][nl] = wv.x * xp[id.x] + wv.y * xp[id.y]
                   + wv.z * xp[id.z] + wv.w * xp[id.w];
    }
    __syncthreads();
    for (int i = threadIdx.x; i < 1024; i += 256) {
        int nl  = i >> 5;
        int ckl = i & 31;                 // lane-varying -> coalesced write
        g_val[(size_t)(b * HW + n0 + nl) * CKDIM + ck0 + ckl] = s[ckl][nl];
    }
}

// ---------------------------------------------------------------------------
// Kernel 3: SGEMM  out[b][o][n] = sum_ck W[o][ck] * val[b][n][ck] + bias[o]
// 128x128 CTA tile, K-chunk 8, 8x8 per-thread microtile (256 threads).
// ---------------------------------------------------------------------------
__global__ __launch_bounds__(256)
void gemm_kernel(const float* __restrict__ weight,
                 const float* __restrict__ bias,
                 float* __restrict__ out)
{
    __shared__ float As[8][128];
    __shared__ float Bs[8][128];

    const int b  = blockIdx.z;
    const int n0 = blockIdx.x * 128;
    const int m0 = blockIdx.y * 128;
    const int tid = threadIdx.x;
    const int tx = tid & 15;     // n direction
    const int ty = tid >> 4;     // m direction

    float acc[8][8];
#pragma unroll
    for (int i = 0; i < 8; i++)
#pragma unroll
        for (int j = 0; j < 8; j++) acc[i][j] = 0.f;

    const float* Bbase = g_val + (size_t)b * HW * CKDIM;
    const int mrow = tid >> 1;           // 0..127
    const int kq   = (tid & 1) * 4;      // 0 or 4

    for (int k0 = 0; k0 < CKDIM; k0 += 8) {
        float4 a = *(const float4*)&weight[(size_t)(m0 + mrow) * CKDIM + k0 + kq];
        float4 v = *(const float4*)&Bbase[(size_t)(n0 + mrow) * CKDIM + k0 + kq];
        As[kq + 0][mrow] = a.x; As[kq + 1][mrow] = a.y;
        As[kq + 2][mrow] = a.z; As[kq + 3][mrow] = a.w;
        Bs[kq + 0][mrow] = v.x; Bs[kq + 1][mrow] = v.y;
        Bs[kq + 2][mrow] = v.z; Bs[kq + 3][mrow] = v.w;
        __syncthreads();

#pragma unroll
        for (int kk = 0; kk < 8; kk++) {
            float ar[8], br[8];
            *(float4*)&ar[0] = *(const float4*)&As[kk][ty * 8];
            *(float4*)&ar[4] = *(const float4*)&As[kk][ty * 8 + 4];
            *(float4*)&br[0] = *(const float4*)&Bs[kk][tx * 8];
            *(float4*)&br[4] = *(const float4*)&Bs[kk][tx * 8 + 4];
#pragma unroll
            for (int i = 0; i < 8; i++)
#pragma unroll
                for (int j = 0; j < 8; j++)
                    acc[i][j] += ar[i] * br[j];
        }
        __syncthreads();
    }

#pragma unroll
    for (int i = 0; i < 8; i++) {
        int o = m0 + ty * 8 + i;
        float bi = bias[o];
        float* op = out + ((size_t)(b * OUTC + o)) * HW + n0 + tx * 8;
        float4 r0 = make_float4(acc[i][0] + bi, acc[i][1] + bi,
                                acc[i][2] + bi, acc[i][3] + bi);
        float4 r1 = make_float4(acc[i][4] + bi, acc[i][5] + bi,
                                acc[i][6] + bi, acc[i][7] + bi);
        *(float4*)&op[0] = r0;
        *(float4*)&op[4] = r1;
    }
}

// ---------------------------------------------------------------------------
// Launch: inputs per metadata order: x, w_off, b_off, weight, bias
// ---------------------------------------------------------------------------
extern "C" void kernel_launch(void* const* d_in, const int* in_sizes, int n_in,
                              void* d_out, int out_size)
{
    const float* x      = (const float*)d_in[0];
    const float* w_off  = (const float*)d_in[1];
    const float* b_off  = (const float*)d_in[2];
    const float* weight = (const float*)d_in[3];
    const float* bias   = (const float*)d_in[4];
    float* out = (float*)d_out;

    // Stage 1: offset conv + sampling records (one thread per b,h,w)
    offset_kernel<<<(BATCH * HW) / 128, 128>>>(x, w_off, b_off);

    // Stage 2: bilinear gather into K-major val matrix
    dim3 ggrid(CKDIM / 32, HW / 32, BATCH);   // 72 x 128 x 4
    gather_kernel<<<ggrid, 256>>>(x);

    // Stage 3: GEMM  (M=256, N=4096 per batch, K=2304)
    dim3 mgrid(HW / 128, OUTC / 128, BATCH);  // 32 x 2 x 4
    gemm_kernel<<<mgrid, 256>>>(weight, bias, out);
}

// round 2
// speedup vs baseline: 1.2997x; 1.2997x over previous
#include <cuda_runtime.h>
#include <cstdint>

// Problem constants
#define BATCH 4
#define CIN   256
#define HDIM  64
#define WDIM  64
#define HW    4096          // 64*64
#define OUTC  256
#define KKPOS 9             // 3x3
#define CKDIM 2304          // CIN * 9
#define NOFF  27            // 3*K*K offset-conv output channels
#define NPIX  (BATCH * HW)  // 16384
#define NCHUNK 8            // channel-split factor for offset conv

// ---------------------------------------------------------------------------
// Scratch (static __device__ arrays: allocation inside kernel_launch is banned)
// ---------------------------------------------------------------------------
// Partial offset-conv accumulators: [chunk][oc][pixel] (coalesced in pixel)
__device__ float g_off_part[NCHUNK * NOFF * NPIX];   // 14.2 MB
// Per-(b, kpos, hw) bilinear sampling record: 4 clamped flat indices into the
// 64x64 plane + 4 bilinear weights (mask folded in, zeroed when out of range).
__device__ int4   g_rec_idx[BATCH * KKPOS * HW];     // 2.36 MB
__device__ float4 g_rec_w  [BATCH * KKPOS * HW];     // 2.36 MB
// Materialized deformable im2col matrix, K-major rows: val[b][hw][ck]
__device__ float  g_val[(size_t)BATCH * HW * CKDIM]; // 151 MB

// ---------------------------------------------------------------------------
// Kernel 1a: offset conv partials. grid=(NPIX/128, NCHUNK).
// Each CTA: 128 pixels x 32 input channels -> partial acc[27].
// ---------------------------------------------------------------------------
__global__ __launch_bounds__(128)
void offset_part_kernel(const float* __restrict__ x,
                        const float* __restrict__ w_off)
{
    __shared__ float s_w[NOFF * 16 * KKPOS];   // 27*16*9 floats = 15.2 KB

    const int gid = blockIdx.x * blockDim.x + threadIdx.x;   // 0..16383
    const int b  = gid >> 12;
    const int hw = gid & 4095;
    const int y  = hw >> 6;
    const int xw = hw & 63;
    const int cbase = blockIdx.y * (CIN / NCHUNK);           // 32-channel slice

    float acc[NOFF];
#pragma unroll
    for (int i = 0; i < NOFF; i++) acc[i] = 0.f;

    const float* xb = x + (size_t)b * CIN * HW;

    for (int sub = 0; sub < 2; sub++) {
        const int c0 = cbase + sub * 16;
        __syncthreads();
        // stage w_off[:, c0:c0+16, :] into smem, layout [oc][cc][j]
        for (int i = threadIdx.x; i < NOFF * 16 * KKPOS; i += blockDim.x) {
            int oc  = i / (16 * KKPOS);
            int rem = i - oc * (16 * KKPOS);          // cc*9 + j
            s_w[i] = w_off[oc * (CIN * KKPOS) + c0 * KKPOS + rem];
        }
        __syncthreads();

        for (int cc = 0; cc < 16; cc++) {
            const float* xp = xb + (size_t)(c0 + cc) * HW;
            float v[9];
#pragma unroll
            for (int j = 0; j < 9; j++) {
                int dy = j / 3 - 1, dx = j % 3 - 1;
                int yy = y + dy, xx = xw + dx;
                v[j] = (yy >= 0 && yy < HDIM && xx >= 0 && xx < WDIM)
                         ? xp[yy * WDIM + xx] : 0.f;
            }
            const float* sw = &s_w[cc * KKPOS];
#pragma unroll
            for (int oc = 0; oc < NOFF; oc++) {
                float s = 0.f;
#pragma unroll
                for (int j = 0; j < 9; j++)
                    s += sw[oc * (16 * KKPOS) + j] * v[j];
                acc[oc] += s;
            }
        }
    }

#pragma unroll
    for (int oc = 0; oc < NOFF; oc++)
        g_off_part[(blockIdx.y * NOFF + oc) * NPIX + gid] = acc[oc];
}

// ---------------------------------------------------------------------------
// Kernel 1b: reduce partials + build sampling records. One thread per pixel.
// ---------------------------------------------------------------------------
__global__ __launch_bounds__(256)
void offset_rec_kernel(const float* __restrict__ b_off)
{
    const int gid = blockIdx.x * blockDim.x + threadIdx.x;   // 0..16383
    const int b  = gid >> 12;
    const int hw = gid & 4095;
    const int y  = hw >> 6;
    const int xw = hw & 63;

    float acc[NOFF];
#pragma unroll
    for (int oc = 0; oc < NOFF; oc++) {
        float s = b_off[oc];
#pragma unroll
        for (int c = 0; c < NCHUNK; c++)
            s += g_off_part[(c * NOFF + oc) * NPIX + gid];
        acc[oc] = s;
    }

    // dy = om[2k], dx = om[2k+1], mask = sigmoid(om[18+k])
#pragma unroll
    for (int kp = 0; kp < KKPOS; kp++) {
        float dy = acc[2 * kp];
        float dx = acc[2 * kp + 1];
        float mask = 1.f / (1.f + __expf(-acc[18 + kp]));

        float py = (float)(y  - 1 + kp / 3) + dy;
        float px = (float)(xw - 1 + kp % 3) + dx;
        float y0f = floorf(py), x0f = floorf(px);
        float ly = py - y0f,   lx = px - x0f;
        int y0 = (int)y0f, x0 = (int)x0f;

        int4 idx; float4 wv;
        {
            int yy = y0, xx = x0;
            bool ok = (yy >= 0 && yy < HDIM && xx >= 0 && xx < WDIM);
            int yc = min(max(yy, 0), HDIM - 1), xc = min(max(xx, 0), WDIM - 1);
            idx.x = yc * WDIM + xc;
            wv.x = ok ? (1.f - ly) * (1.f - lx) * mask : 0.f;
        }
        {
            int yy = y0, xx = x0 + 1;
            bool ok = (yy >= 0 && yy < HDIM && xx >= 0 && xx < WDIM);
            int yc = min(max(yy, 0), HDIM - 1), xc = min(max(xx, 0), WDIM - 1);
            idx.y = yc * WDIM + xc;
            wv.y = ok ? (1.f - ly) * lx * mask : 0.f;
        }
        {
            int yy = y0 + 1, xx = x0;
            bool ok = (yy >= 0 && yy < HDIM && xx >= 0 && xx < WDIM);
            int yc = min(max(yy, 0), HDIM - 1), xc = min(max(xx, 0), WDIM - 1);
            idx.z = yc * WDIM + xc;
            wv.z = ok ? ly * (1.f - lx) * mask : 0.f;
        }
        {
            int yy = y0 + 1, xx = x0 + 1;
            bool ok = (yy >= 0 && yy < HDIM && xx >= 0 && xx < WDIM);
            int yc = min(max(yy, 0), HDIM - 1), xc = min(max(xx, 0), WDIM - 1);
            idx.w = yc * WDIM + xc;
            wv.w = ok ? ly * lx * mask : 0.f;
        }

        int r = ((b * KKPOS + kp) << 12) + hw;
        g_rec_idx[r] = idx;
        g_rec_w[r]   = wv;
    }
}

// ---------------------------------------------------------------------------
// Kernel 2: bilinear gather -> g_val[b][hw][ck]  (K-major rows)
// ---------------------------------------------------------------------------
__global__ __launch_bounds__(256)
void gather_kernel(const float* __restrict__ x)
{
    __shared__ float s[32][33];

    const int b   = blockIdx.z;
    const int n0  = blockIdx.y * 32;     // hw tile
    const int ck0 = blockIdx.x * 32;     // ck tile
    const float* xb = x + (size_t)b * CIN * HW;

    for (int i = threadIdx.x; i < 1024; i += 256) {
        int ckl = i >> 5;                 // fixed per warp
        int nl  = i & 31;                 // lane-varying -> coalesced
        int ck  = ck0 + ckl;
        int c   = ck / KKPOS;
        int kp  = ck - c * KKPOS;
        int n   = n0 + nl;
        int r   = ((b * KKPOS + kp) << 12) + n;
        int4   id = g_rec_idx[r];
        float4 wv = g_rec_w[r];
        const float* xp = xb + (size_t)c * HW;
        s[ckl][nl] = wv.x * xp[id.x] + wv.y * xp[id.y]
                   + wv.z * xp[id.z] + wv.w * xp[id.w];
    }
    __syncthreads();
    for (int i = threadIdx.x; i < 1024; i += 256) {
        int nl  = i >> 5;
        int ckl = i & 31;                 // lane-varying -> coalesced write
        g_val[(size_t)(b * HW + n0 + nl) * CKDIM + ck0 + ckl] = s[ckl][nl];
    }
}

// ---------------------------------------------------------------------------
// Kernel 3: SGEMM  out[b][o][n] = sum_ck W[o][ck] * val[b][n][ck] + bias[o]
// 128x128 CTA tile, K-chunk 8, 8x8 per-thread microtile (256 threads).
// ---------------------------------------------------------------------------
__global__ __launch_bounds__(256)
void gemm_kernel(const float* __restrict__ weight,
                 const float* __restrict__ bias,
                 float* __restrict__ out)
{
    __shared__ float As[8][128];
    __shared__ float Bs[8][128];

    const int b  = blockIdx.z;
    const int n0 = blockIdx.x * 128;
    const int m0 = blockIdx.y * 128;
    const int tid = threadIdx.x;
    const int tx = tid & 15;     // n direction
    const int ty = tid >> 4;     // m direction

    float acc[8][8];
#pragma unroll
    for (int i = 0; i < 8; i++)
#pragma unroll
        for (int j = 0; j < 8; j++) acc[i][j] = 0.f;

    const float* Bbase = g_val + (size_t)b * HW * CKDIM;
    const int mrow = tid >> 1;           // 0..127
    const int kq   = (tid & 1) * 4;      // 0 or 4

    for (int k0 = 0; k0 < CKDIM; k0 += 8) {
        float4 a = *(const float4*)&weight[(size_t)(m0 + mrow) * CKDIM + k0 + kq];
        float4 v = *(const float4*)&Bbase[(size_t)(n0 + mrow) * CKDIM + k0 + kq];
        As[kq + 0][mrow] = a.x; As[kq + 1][mrow] = a.y;
        As[kq + 2][mrow] = a.z; As[kq + 3][mrow] = a.w;
        Bs[kq + 0][mrow] = v.x; Bs[kq + 1][mrow] = v.y;
        Bs[kq + 2][mrow] = v.z; Bs[kq + 3][mrow] = v.w;
        __syncthreads();

#pragma unroll
        for (int kk = 0; kk < 8; kk++) {
            float ar[8], br[8];
            *(float4*)&ar[0] = *(const float4*)&As[kk][ty * 8];
            *(float4*)&ar[4] = *(const float4*)&As[kk][ty * 8 + 4];
            *(float4*)&br[0] = *(const float4*)&Bs[kk][tx * 8];
            *(float4*)&br[4] = *(const float4*)&Bs[kk][tx * 8 + 4];
#pragma unroll
            for (int i = 0; i < 8; i++)
#pragma unroll
                for (int j = 0; j < 8; j++)
                    acc[i][j] += ar[i] * br[j];
        }
        __syncthreads();
    }

#pragma unroll
    for (int i = 0; i < 8; i++) {
        int o = m0 + ty * 8 + i;
        float bi = bias[o];
        float* op = out + ((size_t)(b * OUTC + o)) * HW + n0 + tx * 8;
        float4 r0 = make_float4(acc[i][0] + bi, acc[i][1] + bi,
                                acc[i][2] + bi, acc[i][3] + bi);
        float4 r1 = make_float4(acc[i][4] + bi, acc[i][5] + bi,
                                acc[i][6] + bi, acc[i][7] + bi);
        *(float4*)&op[0] = r0;
        *(float4*)&op[4] = r1;
    }
}

// ---------------------------------------------------------------------------
// Launch: inputs per metadata order: x, w_off, b_off, weight, bias
// ---------------------------------------------------------------------------
extern "C" void kernel_launch(void* const* d_in, const int* in_sizes, int n_in,
                              void* d_out, int out_size)
{
    const float* x      = (const float*)d_in[0];
    const float* w_off  = (const float*)d_in[1];
    const float* b_off  = (const float*)d_in[2];
    const float* weight = (const float*)d_in[3];
    const float* bias   = (const float*)d_in[4];
    float* out = (float*)d_out;

    // Stage 1a: offset conv partials, channel-split 8x for occupancy
    dim3 pgrid(NPIX / 128, NCHUNK);
    offset_part_kernel<<<pgrid, 128>>>(x, w_off);

    // Stage 1b: reduce partials + build sampling records
    offset_rec_kernel<<<NPIX / 256, 256>>>(b_off);

    // Stage 2: bilinear gather into K-major val matrix
    dim3 ggrid(CKDIM / 32, HW / 32, BATCH);   // 72 x 128 x 4
    gather_kernel<<<ggrid, 256>>>(x);

    // Stage 3: GEMM  (M=256, N=4096 per batch, K=2304)
    dim3 mgrid(HW / 128, OUTC / 128, BATCH);  // 32 x 2 x 4
    gemm_kernel<<<mgrid, 256>>>(weight, bias, out);
}

// round 4
// speedup vs baseline: 2.0198x; 1.5540x over previous
#include <cuda_runtime.h>
#include <cstdint>

// Problem constants
#define BATCH 4
#define CIN   256
#define HDIM  64
#define WDIM  64
#define HW    4096          // 64*64
#define OUTC  256
#define KKPOS 9             // 3x3
#define CKDIM 2304          // CIN * 9
#define NOFF  27            // 3*K*K offset-conv output channels
#define NPIX  (BATCH * HW)  // 16384
#define NCHUNK 8            // channel-split factor for offset conv

// GEMM config (mma.sync m16n8k8 tf32)
#define TM 128              // CTA M tile (out channels)
#define TN 128              // CTA N tile (pixels)
#define TK 32               // K per pipeline chunk
#define NSTAGE 3
#define KCHUNKS (CKDIM / TK)              // 72
#define STAGE_FLOATS (2 * TM * TK)        // A(4096) + B(4096) = 8192 floats
#define GEMM_SMEM_BYTES (NSTAGE * STAGE_FLOATS * 4)   // 98304

__device__ __forceinline__ uint32_t smem_u32(const void* p) {
    uint32_t a;
    asm("{ .reg .u64 t; cvta.to.shared.u64 t, %1; cvt.u32.u64 %0, t; }" : "=r"(a) : "l"(p));
    return a;
}
__device__ __forceinline__ void cp16(uint32_t dst, const void* src) {
    asm volatile("cp.async.cg.shared.global [%0], [%1], 16;" :: "r"(dst), "l"(src));
}
__device__ __forceinline__ float to_tf32(float f) {
    uint32_t u;
    asm("cvt.rna.tf32.f32 %0, %1;" : "=r"(u) : "f"(f));
    return __uint_as_float(u);
}
__device__ __forceinline__ void mma_tf32(float* c, const uint32_t* a, const uint32_t* b) {
    asm volatile(
        "mma.sync.aligned.m16n8k8.row.col.f32.tf32.tf32.f32 "
        "{%0,%1,%2,%3}, {%4,%5,%6,%7}, {%8,%9}, {%0,%1,%2,%3};"
        : "+f"(c[0]), "+f"(c[1]), "+f"(c[2]), "+f"(c[3])
        : "r"(a[0]), "r"(a[1]), "r"(a[2]), "r"(a[3]), "r"(b[0]), "r"(b[1]));
}

// ---------------------------------------------------------------------------
// Scratch (static __device__ arrays: allocation inside kernel_launch is banned)
// ---------------------------------------------------------------------------
__device__ float g_off_part[NCHUNK * NOFF * NPIX];   // 14.2 MB
__device__ int4   g_rec_idx[BATCH * KKPOS * HW];     // 2.36 MB
__device__ float4 g_rec_w  [BATCH * KKPOS * HW];     // 2.36 MB
__device__ float  g_val[(size_t)BATCH * HW * CKDIM]; // 151 MB (tf32-rounded)
__device__ float  g_wt[OUTC * CKDIM];                // 2.36 MB (tf32-rounded)

// ---------------------------------------------------------------------------
// Kernel 0: round GEMM weight to tf32 once per launch.
// ---------------------------------------------------------------------------
__global__ __launch_bounds__(256)
void wprep_kernel(const float* __restrict__ weight)
{
    int i = blockIdx.x * 256 + threadIdx.x;
    if (i < OUTC * CKDIM) g_wt[i] = to_tf32(weight[i]);
}

// ---------------------------------------------------------------------------
// Kernel 1a: offset conv partials. grid=(NPIX/128, NCHUNK).
// ---------------------------------------------------------------------------
__global__ __launch_bounds__(128)
void offset_part_kernel(const float* __restrict__ x,
                        const float* __restrict__ w_off)
{
    __shared__ float s_w[NOFF * 16 * KKPOS];

    const int gid = blockIdx.x * blockDim.x + threadIdx.x;
    const int b  = gid >> 12;
    const int hw = gid & 4095;
    const int y  = hw >> 6;
    const int xw = hw & 63;
    const int cbase = blockIdx.y * (CIN / NCHUNK);

    float acc[NOFF];
#pragma unroll
    for (int i = 0; i < NOFF; i++) acc[i] = 0.f;

    const float* xb = x + (size_t)b * CIN * HW;

    for (int sub = 0; sub < 2; sub++) {
        const int c0 = cbase + sub * 16;
        __syncthreads();
        for (int i = threadIdx.x; i < NOFF * 16 * KKPOS; i += blockDim.x) {
            int oc  = i / (16 * KKPOS);
            int rem = i - oc * (16 * KKPOS);
            s_w[i] = w_off[oc * (CIN * KKPOS) + c0 * KKPOS + rem];
        }
        __syncthreads();

        for (int cc = 0; cc < 16; cc++) {
            const float* xp = xb + (size_t)(c0 + cc) * HW;
            float v[9];
#pragma unroll
            for (int j = 0; j < 9; j++) {
                int dy = j / 3 - 1, dx = j % 3 - 1;
                int yy = y + dy, xx = xw + dx;
                v[j] = (yy >= 0 && yy < HDIM && xx >= 0 && xx < WDIM)
                         ? xp[yy * WDIM + xx] : 0.f;
            }
            const float* sw = &s_w[cc * KKPOS];
#pragma unroll
            for (int oc = 0; oc < NOFF; oc++) {
                float s = 0.f;
#pragma unroll
                for (int j = 0; j < 9; j++)
                    s += sw[oc * (16 * KKPOS) + j] * v[j];
                acc[oc] += s;
            }
        }
    }

#pragma unroll
    for (int oc = 0; oc < NOFF; oc++)
        g_off_part[(blockIdx.y * NOFF + oc) * NPIX + gid] = acc[oc];
}

// ---------------------------------------------------------------------------
// Kernel 1b: reduce partials + build sampling records.
// ---------------------------------------------------------------------------
__global__ __launch_bounds__(256)
void offset_rec_kernel(const float* __restrict__ b_off)
{
    const int gid = blockIdx.x * blockDim.x + threadIdx.x;
    const int b  = gid >> 12;
    const int hw = gid & 4095;
    const int y  = hw >> 6;
    const int xw = hw & 63;

    float acc[NOFF];
#pragma unroll
    for (int oc = 0; oc < NOFF; oc++) {
        float s = b_off[oc];
#pragma unroll
        for (int c = 0; c < NCHUNK; c++)
            s += g_off_part[(c * NOFF + oc) * NPIX + gid];
        acc[oc] = s;
    }

#pragma unroll
    for (int kp = 0; kp < KKPOS; kp++) {
        float dy = acc[2 * kp];
        float dx = acc[2 * kp + 1];
        float mask = 1.f / (1.f + __expf(-acc[18 + kp]));

        float py = (float)(y  - 1 + kp / 3) + dy;
        float px = (float)(xw - 1 + kp % 3) + dx;
        float y0f = floorf(py), x0f = floorf(px);
        float ly = py - y0f,   lx = px - x0f;
        int y0 = (int)y0f, x0 = (int)x0f;

        int4 idx; float4 wv;
        {
            int yy = y0, xx = x0;
            bool ok = (yy >= 0 && yy < HDIM && xx >= 0 && xx < WDIM);
            int yc = min(max(yy, 0), HDIM - 1), xc = min(max(xx, 0), WDIM - 1);
            idx.x = yc * WDIM + xc;
            wv.x = ok ? (1.f - ly) * (1.f - lx) * mask : 0.f;
        }
        {
            int yy = y0, xx = x0 + 1;
            bool ok = (yy >= 0 && yy < HDIM && xx >= 0 && xx < WDIM);
            int yc = min(max(yy, 0), HDIM - 1), xc = min(max(xx, 0), WDIM - 1);
            idx.y = yc * WDIM + xc;
            wv.y = ok ? (1.f - ly) * lx * mask : 0.f;
        }
        {
            int yy = y0 + 1, xx = x0;
            bool ok = (yy >= 0 && yy < HDIM && xx >= 0 && xx < WDIM);
            int yc = min(max(yy, 0), HDIM - 1), xc = min(max(xx, 0), WDIM - 1);
            idx.z = yc * WDIM + xc;
            wv.z = ok ? ly * (1.f - lx) * mask : 0.f;
        }
        {
            int yy = y0 + 1, xx = x0 + 1;
            bool ok = (yy >= 0 && yy < HDIM && xx >= 0 && xx < WDIM);
            int yc = min(max(yy, 0), HDIM - 1), xc = min(max(xx, 0), WDIM - 1);
            idx.w = yc * WDIM + xc;
            wv.w = ok ? ly * lx * mask : 0.f;
        }

        int r = ((b * KKPOS + kp) << 12) + hw;
        g_rec_idx[r] = idx;
        g_rec_w[r]   = wv;
    }
}

// ---------------------------------------------------------------------------
// Kernel 2: bilinear gather -> g_val[b][hw][ck] (K-major rows, tf32-rounded)
// ---------------------------------------------------------------------------
__global__ __launch_bounds__(256)
void gather_kernel(const float* __restrict__ x)
{
    __shared__ float s[32][33];

    const int b   = blockIdx.z;
    const int n0  = blockIdx.y * 32;
    const int ck0 = blockIdx.x * 32;
    const float* xb = x + (size_t)b * CIN * HW;

    for (int i = threadIdx.x; i < 1024; i += 256) {
        int ckl = i >> 5;
        int nl  = i & 31;
        int ck  = ck0 + ckl;
        int c   = ck / KKPOS;
        int kp  = ck - c * KKPOS;
        int n   = n0 + nl;
        int r   = ((b * KKPOS + kp) << 12) + n;
        int4   id = g_rec_idx[r];
        float4 wv = g_rec_w[r];
        const float* xp = xb + (size_t)c * HW;
        s[ckl][nl] = to_tf32(wv.x * xp[id.x] + wv.y * xp[id.y]
                           + wv.z * xp[id.z] + wv.w * xp[id.w]);
    }
    __syncthreads();
    for (int i = threadIdx.x; i < 1024; i += 256) {
        int nl  = i >> 5;
        int ckl = i & 31;
        g_val[(size_t)(b * HW + n0 + nl) * CKDIM + ck0 + ckl] = s[ckl][nl];
    }
}

// ---------------------------------------------------------------------------
// Kernel 3: tf32 mma.sync GEMM.
// out[b][o][n] = sum_ck g_wt[o][ck] * g_val[n][ck] + bias[o]
// CTA 128x128xK, 3-stage cp.async pipeline. SMEM layout per stage:
// A[kc][m] float4 (kc=k/4: 8 x 128), then B[kc][n] float4 — fragment loads
// become lane-consecutive conflict-free lds.32.
// 8 warps: wm=wid&1 (64 M rows), wn=wid>>1 (32 N cols); warp tile 64x32.
// ---------------------------------------------------------------------------
__device__ __forceinline__ void gemm_fill(float* sm, int stage, int chunk,
                                          int tid, int m0, int n0)
{
    const int k0 = chunk * TK;
    uint32_t sa = smem_u32(sm + stage * STAGE_FLOATS);
    uint32_t sb = sa + TM * TK * 4;     // bytes

    // A: 128 rows x 8 kc-chunks; c = m*8 + kc  (gmem coalesced: 8 thr = 1 row)
#pragma unroll
    for (int it = 0; it < 4; it++) {
        int c = tid + it * 256;
        int m = c >> 3, kc = c & 7;
        cp16(sa + (uint32_t)(kc * 128 + m) * 16,
             g_wt + (size_t)(m0 + m) * CKDIM + k0 + kc * 4);
    }
    // B: 128 rows x 8 kc-chunks
#pragma unroll
    for (int it = 0; it < 4; it++) {
        int c = tid + it * 256;
        int n = c >> 3, kc = c & 7;
        cp16(sb + (uint32_t)(kc * 128 + n) * 16,
             g_val + (size_t)(n0 + n) * CKDIM + k0 + kc * 4);
    }
    asm volatile("cp.async.commit_group;" ::: "memory");
}

__global__ __launch_bounds__(256)
void gemm_mma_kernel(const float* __restrict__ bias,
                     float* __restrict__ out)
{
    extern __shared__ float sm[];
    const int tid = threadIdx.x;
    const int wid = tid >> 5;
    const int lid = tid & 31;
    const int g   = lid >> 2;      // group id 0..7
    const int t4  = lid & 3;       // thread-in-group
    const int wm  = wid & 1;       // M half (64 rows)
    const int wn  = wid >> 1;      // N quarter (32 cols)
    const int n0  = blockIdx.x * TN;
    const int m0  = blockIdx.y * TM;

    float acc[4][4][4];
#pragma unroll
    for (int i = 0; i < 4; i++)
#pragma unroll
        for (int j = 0; j < 4; j++)
#pragma unroll
            for (int q = 0; q < 4; q++) acc[i][j][q] = 0.f;

    // prefetch stages 0..NSTAGE-2
    for (int pf = 0; pf < NSTAGE - 1; pf++)
        gemm_fill(sm, pf, pf, tid, m0, n0);

    for (int i = 0; i < KCHUNKS; i++) {
        const int s = i % NSTAGE;
        if (i == KCHUNKS - 1)
            asm volatile("cp.async.wait_group 0;" ::: "memory");
        else
            asm volatile("cp.async.wait_group %0;" :: "n"(NSTAGE - 2) : "memory");
        __syncthreads();

        // refill the stage freed at the end of the previous iteration
        if (i + NSTAGE - 1 < KCHUNKS)
            gemm_fill(sm, (i + NSTAGE - 1) % NSTAGE, i + NSTAGE - 1, tid, m0, n0);

        const uint32_t* Au = (const uint32_t*)(sm + s * STAGE_FLOATS);
        const uint32_t* Bu = Au + TM * TK;

#pragma unroll
        for (int ks = 0; ks < 4; ks++) {
            const int kc0 = 2 * ks, kc1 = 2 * ks + 1;
            uint32_t af[4][4], bf[4][2];
#pragma unroll
            for (int ii = 0; ii < 4; ii++) {
                int m = wm * 64 + ii * 16 + g;
                af[ii][0] = Au[kc0 * 512 + m * 4 + t4];
                af[ii][1] = Au[kc0 * 512 + (m + 8) * 4 + t4];
                af[ii][2] = Au[kc1 * 512 + m * 4 + t4];
                af[ii][3] = Au[kc1 * 512 + (m + 8) * 4 + t4];
            }
#pragma unroll
            for (int jj = 0; jj < 4; jj++) {
                int n = wn * 32 + jj * 8 + g;
                bf[jj][0] = Bu[kc0 * 512 + n * 4 + t4];
                bf[jj][1] = Bu[kc1 * 512 + n * 4 + t4];
            }
#pragma unroll
            for (int ii = 0; ii < 4; ii++)
#pragma unroll
                for (int jj = 0; jj < 4; jj++)
                    mma_tf32(acc[ii][jj], af[ii], bf[jj]);
        }
    }

    // Epilogue: add bias, store. Pixel block stays within one batch.
    const int b   = n0 >> 12;
    const int hw0 = n0 & 4095;
#pragma unroll
    for (int ii = 0; ii < 4; ii++) {
        int r0 = m0 + wm * 64 + ii * 16 + g;
        float bi0 = bias[r0], bi1 = bias[r0 + 8];
        float* p0 = out + ((size_t)(b * OUTC + r0)) * HW + hw0;
        float* p1 = p0 + (size_t)8 * HW;
#pragma unroll
        for (int jj = 0; jj < 4; jj++) {
            int col = wn * 32 + jj * 8 + 2 * t4;
            float2 v0 = make_float2(acc[ii][jj][0] + bi0, acc[ii][jj][1] + bi0);
            float2 v1 = make_float2(acc[ii][jj][2] + bi1, acc[ii][jj][3] + bi1);
            *(float2*)(p0 + col) = v0;
            *(float2*)(p1 + col) = v1;
        }
    }
}

// ---------------------------------------------------------------------------
// Launch: inputs per metadata order: x, w_off, b_off, weight, bias
// ---------------------------------------------------------------------------
extern "C" void kernel_launch(void* const* d_in, const int* in_sizes, int n_in,
                              void* d_out, int out_size)
{
    const float* x      = (const float*)d_in[0];
    const float* w_off  = (const float*)d_in[1];
    const float* b_off  = (const float*)d_in[2];
    const float* weight = (const float*)d_in[3];
    const float* bias   = (const float*)d_in[4];
    float* out = (float*)d_out;

    cudaFuncSetAttribute(gemm_mma_kernel,
                         cudaFuncAttributeMaxDynamicSharedMemorySize,
                         GEMM_SMEM_BYTES);

    wprep_kernel<<<(OUTC * CKDIM + 255) / 256, 256>>>(weight);

    dim3 pgrid(NPIX / 128, NCHUNK);
    offset_part_kernel<<<pgrid, 128>>>(x, w_off);

    offset_rec_kernel<<<NPIX / 256, 256>>>(b_off);

    dim3 ggrid(CKDIM / 32, HW / 32, BATCH);
    gather_kernel<<<ggrid, 256>>>(x);

    dim3 mgrid(NPIX / TN, OUTC / TM);   // 128 x 2
    gemm_mma_kernel<<<mgrid, 256, GEMM_SMEM_BYTES>>>(bias, out);
}

// round 5
// speedup vs baseline: 2.5131x; 1.2442x over previous
#include <cuda_runtime.h>
#include <cstdint>

// Problem constants
#define BATCH 4
#define CIN   256
#define HDIM  64
#define WDIM  64
#define HW    4096          // 64*64
#define OUTC  256
#define KKPOS 9             // 3x3
#define CKDIM 2304          // CIN * 9
#define NOFF  27            // 3*K*K offset-conv output channels
#define NPIX  (BATCH * HW)  // 16384
#define NCHUNK 8            // channel-split factor for offset conv

// Fused GEMM config (mma.sync m16n8k8 tf32)
#define TM 256              // CTA M tile (ALL out channels)
#define TN 128              // CTA N tile (pixels)
#define TK 32               // K per pipeline chunk
#define NSTAGE 3
#define KCHUNKS (CKDIM / TK)                  // 72
#define A_FLOATS (TM * TK)                    // 8192
#define B_FLOATS (TN * TK)                    // 4096
#define STAGE_FLOATS (A_FLOATS + B_FLOATS)    // 12288 (48 KB)
#define REC_OFF (NSTAGE * STAGE_FLOATS)       // float offset of record area
// record area: 1152 int4 (4608 floats) + 1152 float4 (4608 floats)
#define GEMM_SMEM_BYTES ((REC_OFF + 2 * 4608) * 4)   // 184320

__device__ __forceinline__ uint32_t smem_u32(const void* p) {
    uint32_t a;
    asm("{ .reg .u64 t; cvta.to.shared.u64 t, %1; cvt.u32.u64 %0, t; }" : "=r"(a) : "l"(p));
    return a;
}
__device__ __forceinline__ void cp16(uint32_t dst, const void* src) {
    asm volatile("cp.async.cg.shared.global [%0], [%1], 16;" :: "r"(dst), "l"(src));
}
__device__ __forceinline__ float to_tf32(float f) {
    uint32_t u;
    asm("cvt.rna.tf32.f32 %0, %1;" : "=r"(u) : "f"(f));
    return __uint_as_float(u);
}
__device__ __forceinline__ void mma_tf32(float* c, const uint32_t* a, const uint32_t* b) {
    asm volatile(
        "mma.sync.aligned.m16n8k8.row.col.f32.tf32.tf32.f32 "
        "{%0,%1,%2,%3}, {%4,%5,%6,%7}, {%8,%9}, {%0,%1,%2,%3};"
        : "+f"(c[0]), "+f"(c[1]), "+f"(c[2]), "+f"(c[3])
        : "r"(a[0]), "r"(a[1]), "r"(a[2]), "r"(a[3]), "r"(b[0]), "r"(b[1]));
}

// ---------------------------------------------------------------------------
// Scratch (static __device__ arrays: allocation inside kernel_launch is banned)
// ---------------------------------------------------------------------------
__device__ float g_off_part[NCHUNK * NOFF * NPIX];   // 14.2 MB
__device__ int4   g_rec_idx[BATCH * KKPOS * HW];     // 2.36 MB
__device__ float4 g_rec_w  [BATCH * KKPOS * HW];     // 2.36 MB
__device__ float  g_wt[OUTC * CKDIM];                // 2.36 MB (tf32-rounded)

// ---------------------------------------------------------------------------
// Kernel 0: round GEMM weight to tf32 once per launch.
// ---------------------------------------------------------------------------
__global__ __launch_bounds__(256)
void wprep_kernel(const float* __restrict__ weight)
{
    int i = blockIdx.x * 256 + threadIdx.x;
    if (i < OUTC * CKDIM) g_wt[i] = to_tf32(weight[i]);
}

// ---------------------------------------------------------------------------
// Kernel 1a: offset conv partials. grid=(NPIX/128, NCHUNK).
// ---------------------------------------------------------------------------
__global__ __launch_bounds__(128)
void offset_part_kernel(const float* __restrict__ x,
                        const float* __restrict__ w_off)
{
    __shared__ float s_w[NOFF * 16 * KKPOS];

    const int gid = blockIdx.x * blockDim.x + threadIdx.x;
    const int b  = gid >> 12;
    const int hw = gid & 4095;
    const int y  = hw >> 6;
    const int xw = hw & 63;
    const int cbase = blockIdx.y * (CIN / NCHUNK);

    float acc[NOFF];
#pragma unroll
    for (int i = 0; i < NOFF; i++) acc[i] = 0.f;

    const float* xb = x + (size_t)b * CIN * HW;

    for (int sub = 0; sub < 2; sub++) {
        const int c0 = cbase + sub * 16;
        __syncthreads();
        for (int i = threadIdx.x; i < NOFF * 16 * KKPOS; i += blockDim.x) {
            int oc  = i / (16 * KKPOS);
            int rem = i - oc * (16 * KKPOS);
            s_w[i] = w_off[oc * (CIN * KKPOS) + c0 * KKPOS + rem];
        }
        __syncthreads();

        for (int cc = 0; cc < 16; cc++) {
            const float* xp = xb + (size_t)(c0 + cc) * HW;
            float v[9];
#pragma unroll
            for (int j = 0; j < 9; j++) {
                int dy = j / 3 - 1, dx = j % 3 - 1;
                int yy = y + dy, xx = xw + dx;
                v[j] = (yy >= 0 && yy < HDIM && xx >= 0 && xx < WDIM)
                         ? xp[yy * WDIM + xx] : 0.f;
            }
            const float* sw = &s_w[cc * KKPOS];
#pragma unroll
            for (int oc = 0; oc < NOFF; oc++) {
                float s = 0.f;
#pragma unroll
                for (int j = 0; j < 9; j++)
                    s += sw[oc * (16 * KKPOS) + j] * v[j];
                acc[oc] += s;
            }
        }
    }

#pragma unroll
    for (int oc = 0; oc < NOFF; oc++)
        g_off_part[(blockIdx.y * NOFF + oc) * NPIX + gid] = acc[oc];
}

// ---------------------------------------------------------------------------
// Kernel 1b: reduce partials + build sampling records.
// ---------------------------------------------------------------------------
__global__ __launch_bounds__(256)
void offset_rec_kernel(const float* __restrict__ b_off)
{
    const int gid = blockIdx.x * blockDim.x + threadIdx.x;
    const int b  = gid >> 12;
    const int hw = gid & 4095;
    const int y  = hw >> 6;
    const int xw = hw & 63;

    float acc[NOFF];
#pragma unroll
    for (int oc = 0; oc < NOFF; oc++) {
        float s = b_off[oc];
#pragma unroll
        for (int c = 0; c < NCHUNK; c++)
            s += g_off_part[(c * NOFF + oc) * NPIX + gid];
        acc[oc] = s;
    }

#pragma unroll
    for (int kp = 0; kp < KKPOS; kp++) {
        float dy = acc[2 * kp];
        float dx = acc[2 * kp + 1];
        float mask = 1.f / (1.f + __expf(-acc[18 + kp]));

        float py = (float)(y  - 1 + kp / 3) + dy;
        float px = (float)(xw - 1 + kp % 3) + dx;
        float y0f = floorf(py), x0f = floorf(px);
        float ly = py - y0f,   lx = px - x0f;
        int y0 = (int)y0f, x0 = (int)x0f;

        int4 idx; float4 wv;
        {
            int yy = y0, xx = x0;
            bool ok = (yy >= 0 && yy < HDIM && xx >= 0 && xx < WDIM);
            int yc = min(max(yy, 0), HDIM - 1), xc = min(max(xx, 0), WDIM - 1);
            idx.x = yc * WDIM + xc;
            wv.x = ok ? (1.f - ly) * (1.f - lx) * mask : 0.f;
        }
        {
            int yy = y0, xx = x0 + 1;
            bool ok = (yy >= 0 && yy < HDIM && xx >= 0 && xx < WDIM);
            int yc = min(max(yy, 0), HDIM - 1), xc = min(max(xx, 0), WDIM - 1);
            idx.y = yc * WDIM + xc;
            wv.y = ok ? (1.f - ly) * lx * mask : 0.f;
        }
        {
            int yy = y0 + 1, xx = x0;
            bool ok = (yy >= 0 && yy < HDIM && xx >= 0 && xx < WDIM);
            int yc = min(max(yy, 0), HDIM - 1), xc = min(max(xx, 0), WDIM - 1);
            idx.z = yc * WDIM + xc;
            wv.z = ok ? ly * (1.f - lx) * mask : 0.f;
        }
        {
            int yy = y0 + 1, xx = x0 + 1;
            bool ok = (yy >= 0 && yy < HDIM && xx >= 0 && xx < WDIM);
            int yc = min(max(yy, 0), HDIM - 1), xc = min(max(xx, 0), WDIM - 1);
            idx.w = yc * WDIM + xc;
            wv.w = ok ? ly * lx * mask : 0.f;
        }

        int r = ((b * KKPOS + kp) << 12) + hw;
        g_rec_idx[r] = idx;
        g_rec_w[r]   = wv;
    }
}

// ---------------------------------------------------------------------------
// Kernel 2 (fused): gather + tf32 mma.sync GEMM.
// out[b][o][n] = sum_ck g_wt[o][ck] * val(n, ck) + bias[o]
// CTA: M=256 x N=128 pixels x K=2304. 512 threads (16 warps, 4x4 warp grid,
// warp tile 64x32). A staged via cp.async; B tile COMPUTED per chunk from
// SMEM-resident sampling records + x (L2-hot). 3-stage rotation:
// stage i+2 filled in iter i (after MMA), consumed in iter i+2.
// SMEM per stage: A[kc][m] float4 (8x256), B[kc][n] float4 (8x128).
// ---------------------------------------------------------------------------
__device__ __forceinline__ void fill_A(float* sm, int stage, int chunk, int tid)
{
    const int k0 = chunk * TK;
    uint32_t sa = smem_u32(sm + stage * STAGE_FLOATS);
    // 256 rows x 8 kc-chunks = 2048 cp16; 512 threads -> 4 each
#pragma unroll
    for (int it = 0; it < 4; it++) {
        int c = tid + it * 512;
        int m = c >> 3, kc = c & 7;
        cp16(sa + (uint32_t)(kc * TM + m) * 16,
             g_wt + (size_t)m * CKDIM + k0 + kc * 4);
    }
    asm volatile("cp.async.commit_group;" ::: "memory");
}

__device__ __forceinline__ void fill_B(float* sm, int stage, int chunk, int tid,
                                       const float* __restrict__ xb,
                                       const int4* s_idx, const float4* s_w)
{
    const int k0 = chunk * TK;
    float* sb = sm + stage * STAGE_FLOATS + A_FLOATS;
    // 128 pixels x 8 kc = 1024 float4 cells; 512 threads -> 2 each.
    // lane-varying n => coalesced x gathers + conflict-free rec reads/STS.
#pragma unroll
    for (int it = 0; it < 2; it++) {
        int p  = tid + it * 512;
        int n  = p & 127;
        int kc = p >> 7;
        float v[4];
#pragma unroll
        for (int q = 0; q < 4; q++) {
            int ck = k0 + kc * 4 + q;
            int c  = ck / KKPOS;
            int kp = ck - c * KKPOS;
            int4   id = s_idx[kp * TN + n];
            float4 w  = s_w [kp * TN + n];
            const float* xp = xb + (size_t)c * HW;
            v[q] = to_tf32(w.x * xp[id.x] + w.y * xp[id.y]
                         + w.z * xp[id.z] + w.w * xp[id.w]);
        }
        *(float4*)&sb[(kc * TN + n) * 4] = make_float4(v[0], v[1], v[2], v[3]);
    }
}

__global__ __launch_bounds__(512, 1)
void gemm_fused_kernel(const float* __restrict__ x,
                       const float* __restrict__ bias,
                       float* __restrict__ out)
{
    extern __shared__ float sm[];
    const int tid = threadIdx.x;
    const int wid = tid >> 5;
    const int lid = tid & 31;
    const int g   = lid >> 2;      // group id 0..7
    const int t4  = lid & 3;       // thread-in-group
    const int wm  = wid & 3;       // M quarter (64 rows)
    const int wn  = wid >> 2;      // N quarter (32 cols)
    const int n0  = blockIdx.x * TN;
    const int b   = n0 >> 12;
    const int hw0 = n0 & 4095;
    const float* xb = x + (size_t)b * CIN * HW;

    int4*   s_idx = (int4*)  (sm + REC_OFF);
    float4* s_w   = (float4*)(sm + REC_OFF + 4608);

    // Preload all 9*128 sampling records for this CTA's pixels.
    for (int i = tid; i < KKPOS * TN; i += 512) {
        int kp = i >> 7, n = i & 127;
        int r  = ((b * KKPOS + kp) << 12) + hw0 + n;
        s_idx[i] = g_rec_idx[r];
        s_w[i]   = g_rec_w[r];
    }
    __syncthreads();

    float acc[4][4][4];
#pragma unroll
    for (int i = 0; i < 4; i++)
#pragma unroll
        for (int j = 0; j < 4; j++)
#pragma unroll
            for (int q = 0; q < 4; q++) acc[i][j][q] = 0.f;

    // Prefetch: A chunks 0,1 (cp.async) and B chunks 0,1 (computed).
    fill_A(sm, 0, 0, tid);
    fill_A(sm, 1, 1, tid);
    fill_B(sm, 0, 0, tid, xb, s_idx, s_w);
    fill_B(sm, 1, 1, tid, xb, s_idx, s_w);

    for (int i = 0; i < KCHUNKS; i++) {
        const int s = i % NSTAGE;
        if (i == KCHUNKS - 1)
            asm volatile("cp.async.wait_group 0;" ::: "memory");
        else
            asm volatile("cp.async.wait_group 1;" ::: "memory");
        __syncthreads();

        if (i + 2 < KCHUNKS)
            fill_A(sm, (i + 2) % NSTAGE, i + 2, tid);

        const uint32_t* Au = (const uint32_t*)(sm + s * STAGE_FLOATS);
        const uint32_t* Bu = Au + A_FLOATS;

#pragma unroll
        for (int ks = 0; ks < 4; ks++) {
            const int kc0 = 2 * ks, kc1 = 2 * ks + 1;
            uint32_t af[4][4], bf[4][2];
#pragma unroll
            for (int ii = 0; ii < 4; ii++) {
                int m = wm * 64 + ii * 16 + g;
                af[ii][0] = Au[kc0 * (TM * 4) + m * 4 + t4];
                af[ii][1] = Au[kc0 * (TM * 4) + (m + 8) * 4 + t4];
                af[ii][2] = Au[kc1 * (TM * 4) + m * 4 + t4];
                af[ii][3] = Au[kc1 * (TM * 4) + (m + 8) * 4 + t4];
            }
#pragma unroll
            for (int jj = 0; jj < 4; jj++) {
                int n = wn * 32 + jj * 8 + g;
                bf[jj][0] = Bu[kc0 * (TN * 4) + n * 4 + t4];
                bf[jj][1] = Bu[kc1 * (TN * 4) + n * 4 + t4];
            }
#pragma unroll
            for (int ii = 0; ii < 4; ii++)
#pragma unroll
                for (int jj = 0; jj < 4; jj++)
                    mma_tf32(acc[ii][jj], af[ii], bf[jj]);
        }

        // Produce B for chunk i+2 after MMA so gather latency overlaps
        // other warps' tensor work; stores drained by next iteration's sync.
        if (i + 2 < KCHUNKS)
            fill_B(sm, (i + 2) % NSTAGE, i + 2, tid, xb, s_idx, s_w);
    }

    // Epilogue: add bias, store (pixel block stays within one batch).
#pragma unroll
    for (int ii = 0; ii < 4; ii++) {
        int r0 = wm * 64 + ii * 16 + g;
        float bi0 = bias[r0], bi1 = bias[r0 + 8];
        float* p0 = out + ((size_t)(b * OUTC + r0)) * HW + hw0;
        float* p1 = p0 + (size_t)8 * HW;
#pragma unroll
        for (int jj = 0; jj < 4; jj++) {
            int col = wn * 32 + jj * 8 + 2 * t4;
            float2 v0 = make_float2(acc[ii][jj][0] + bi0, acc[ii][jj][1] + bi0);
            float2 v1 = make_float2(acc[ii][jj][2] + bi1, acc[ii][jj][3] + bi1);
            *(float2*)(p0 + col) = v0;
            *(float2*)(p1 + col) = v1;
        }
    }
}

// ---------------------------------------------------------------------------
// Launch: inputs per metadata order: x, w_off, b_off, weight, bias
// ---------------------------------------------------------------------------
extern "C" void kernel_launch(void* const* d_in, const int* in_sizes, int n_in,
                              void* d_out, int out_size)
{
    const float* x      = (const float*)d_in[0];
    const float* w_off  = (const float*)d_in[1];
    const float* b_off  = (const float*)d_in[2];
    const float* weight = (const float*)d_in[3];
    const float* bias   = (const float*)d_in[4];
    float* out = (float*)d_out;

    cudaFuncSetAttribute(gemm_fused_kernel,
                         cudaFuncAttributeMaxDynamicSharedMemorySize,
                         GEMM_SMEM_BYTES);

    wprep_kernel<<<(OUTC * CKDIM + 255) / 256, 256>>>(weight);

    dim3 pgrid(NPIX / 128, NCHUNK);
    offset_part_kernel<<<pgrid, 128>>>(x, w_off);

    offset_rec_kernel<<<NPIX / 256, 256>>>(b_off);

    gemm_fused_kernel<<<NPIX / TN, 512, GEMM_SMEM_BYTES>>>(x, bias, out);
}